// round 16
// baseline (speedup 1.0000x reference)
#include <cuda_runtime.h>
#include <cuda_fp16.h>
#include <cstdint>
#include <math.h>

// ---------------------------------------------------------------------------
// Problem constants
// ---------------------------------------------------------------------------
#define B_ 4
#define L_ 2048
#define D_ 256
#define H_ 4096
#define M_ (B_ * L_)          // 8192
#define CHUNK_ 128
#define NC_ (L_ / CHUNK_)     // 16

// ---------------------------------------------------------------------------
// Scratch (device globals; no allocation allowed)
// g_b front 64MB: b fp16 [M,H]. Back region (offset 16M floats): GEMM2
// split-K fp32 partials (2 x M x D). Disjoint lifetimes guaranteed by layout.
// ---------------------------------------------------------------------------
__device__ __align__(256) float  g_b[(size_t)M_ * H_];      // 128 MB arena
__device__ __align__(256) __half g_hh[(size_t)M_ * H_];     // h fp16
__device__ __align__(256) __half g_xh[(size_t)M_ * D_];
__device__ __align__(256) __half g_wbh[(size_t)H_ * D_];
__device__ __align__(256) __half g_wch[(size_t)D_ * H_];
__device__ __align__(256) float  g_carry[B_ * NC_ * H_];
__device__ __align__(256) float  g_hprev[B_ * NC_ * H_];

// ---------------------------------------------------------------------------
// PTX helpers (baseline ISA only: cp.async / ldmatrix / mma.sync)
// ---------------------------------------------------------------------------
__device__ __forceinline__ uint32_t smem_to_u32(const void* p) {
    uint32_t a;
    asm("{ .reg .u64 t; cvta.to.shared.u64 t, %1; cvt.u32.u64 %0, t; }" : "=r"(a) : "l"(p));
    return a;
}
__device__ __forceinline__ void cp_async16(uint32_t dst, const void* src) {
    asm volatile("cp.async.cg.shared.global [%0], [%1], 16;" :: "r"(dst), "l"(src) : "memory");
}
__device__ __forceinline__ void cp_commit() {
    asm volatile("cp.async.commit_group;" ::: "memory");
}
__device__ __forceinline__ void cp_wait4() {
    asm volatile("cp.async.wait_group 4;" ::: "memory");
}
__device__ __forceinline__ void ldsm_x4(uint32_t* r, uint32_t addr) {
    asm volatile("ldmatrix.sync.aligned.m8n8.x4.shared.b16 {%0,%1,%2,%3}, [%4];"
                 : "=r"(r[0]), "=r"(r[1]), "=r"(r[2]), "=r"(r[3]) : "r"(addr));
}
__device__ __forceinline__ void mma_f16(float* c, const uint32_t* a, const uint32_t* b) {
    asm volatile(
        "mma.sync.aligned.m16n8k16.row.col.f32.f16.f16.f32 "
        "{%0,%1,%2,%3}, {%4,%5,%6,%7}, {%8,%9}, {%0,%1,%2,%3};"
        : "+f"(c[0]), "+f"(c[1]), "+f"(c[2]), "+f"(c[3])
        : "r"(a[0]), "r"(a[1]), "r"(a[2]), "r"(a[3]), "r"(b[0]), "r"(b[1]));
}

// Swizzle: 64B rows, 4x 16B lanes; lane ^= (row%4) ^ ((row/4)%4)
__device__ __forceinline__ uint32_t sw_off(int row, int lane) {
    return (uint32_t)(row * 64 + ((lane ^ (row & 3) ^ ((row >> 2) & 3)) << 4));
}

__device__ __forceinline__ float dsigmoid(float x) { return 1.0f / (1.0f + expf(-x)); }

// Output store helpers
__device__ __forceinline__ void store2(float* C, size_t off, float vx, float vy) {
    *reinterpret_cast<float2*>(C + off) = make_float2(vx, vy);
}
__device__ __forceinline__ void store2(__half* C, size_t off, float vx, float vy) {
    *reinterpret_cast<__half2*>(C + off) = __floats2half2_rn(vx, vy);
}

// ---------------------------------------------------------------------------
// Merged fp32 -> fp16 convert: x (n1), WB (n2), WC (n3) in one launch.
// ---------------------------------------------------------------------------
__global__ void conv_all_h(const float* __restrict__ s1, __half* __restrict__ d1, int n1,
                           const float* __restrict__ s2, __half* __restrict__ d2, int n2,
                           const float* __restrict__ s3, __half* __restrict__ d3, int n3)
{
    int i = blockIdx.x * blockDim.x + threadIdx.x;
    const float* s; __half* d; int j = i;
    if (j < n1) { s = s1; d = d1; }
    else if ((j -= n1) < n2) { s = s2; d = d2; }
    else if ((j -= n2) < n3) { s = s3; d = d3; }
    else return;
    float4 v = reinterpret_cast<const float4*>(s)[j];
    reinterpret_cast<__half2*>(d)[2 * j + 0] = __halves2half2(__float2half_rn(v.x), __float2half_rn(v.y));
    reinterpret_cast<__half2*>(d)[2 * j + 1] = __halves2half2(__float2half_rn(v.z), __float2half_rn(v.w));
}

// ---------------------------------------------------------------------------
// Single-stream fp16 GEMM (NT) via mma.sync, templated output type:
//   C[M,N] (+)= Aw[M,Klen] @ (Bw[N,Klen])^T (+ bias[N])
// BM=128, BN=128, BK=32; 8 warps (4m x 2n), warp tile 32x64.
// 6-stage cp.async pipeline; 16KB/stage -> 96KB smem -> 2 CTAs/SM.
// Mainloop: ALL 12 LDSM for both k-steps batched up-front (MLP on smem
// loads), then an unbroken 32-MMA run. Frags 48 + acc 64 = 112 regs.
// ---------------------------------------------------------------------------
#define BM_ 128
#define BN_ 128
#define BK_ 32
#define NSTAGE_ 6
#define STG_ 16384
#define T_A 0
#define T_B 8192

__device__ __forceinline__ void load_stage(
    uint32_t st, int tid, const char* Aw, const char* Bw,
    size_t rowbytes, int bm, int bn, int k0byte)
{
#pragma unroll
    for (int i = 0; i < 2; i++) {
        int l = tid + i * 256;          // 0..511 lanes of 16B
        int r = l >> 2, c = l & 3;
        uint32_t sw = sw_off(r, c);
        size_t ga = (size_t)(bm + r) * rowbytes + k0byte + c * 16;
        size_t gb = (size_t)(bn + r) * rowbytes + k0byte + c * 16;
        cp_async16(st + T_A + sw, Aw + ga);
        cp_async16(st + T_B + sw, Bw + gb);
    }
}

template <typename TOut>
__global__ __launch_bounds__(256, 2)
void gemm_fp16(const __half* __restrict__ Aw, const __half* __restrict__ Bw,
               const float* __restrict__ bias, TOut* __restrict__ C,
               int N, int K, int Klen, size_t zstride)
{
    extern __shared__ char smem[];
    const uint32_t sb = smem_to_u32(smem);
    const int tid = threadIdx.x;
    const int wid = tid >> 5, lid = tid & 31;
    const int wm = wid & 3, wn = wid >> 2;        // 4(m) x 2(n) warp grid
    const int bm = blockIdx.y * BM_;
    const int bn = blockIdx.x * BN_;
    const size_t rowbytes = (size_t)K * 2;
    const int NKC = Klen / BK_;
    const size_t kofs = (size_t)blockIdx.z * Klen * 2;

    const char* pA = (const char*)Aw + kofs;
    const char* pB = (const char*)Bw + kofs;
    C += (size_t)blockIdx.z * zstride;

    float acc[2][8][4];
#pragma unroll
    for (int mt = 0; mt < 2; mt++)
#pragma unroll
        for (int nt = 0; nt < 8; nt++)
#pragma unroll
            for (int j = 0; j < 4; j++) acc[mt][nt][j] = 0.0f;

    // Precomputed fragment smem row/lane bases (kst-invariant parts)
    const int arow0 = wm * 32 + (lid & 15);
    const int alane = (lid >> 4);
    const int brow0 = wn * 64 + (lid & 7) + ((lid >> 4) << 3);
    const int blane = ((lid >> 3) & 1);

    // Prologue: stages 0..4
#pragma unroll
    for (int s = 0; s < NSTAGE_ - 1; s++) {
        if (s < NKC) load_stage(sb + s * STG_, tid, pA, pB, rowbytes, bm, bn, s * BK_ * 2);
        cp_commit();
    }

#pragma unroll 1
    for (int kc = 0; kc < NKC; kc++) {
        cp_wait4();
        __syncthreads();
        {
            int nx = kc + NSTAGE_ - 1;
            if (nx < NKC)
                load_stage(sb + (nx % NSTAGE_) * STG_, tid, pA, pB, rowbytes, bm, bn, nx * BK_ * 2);
            cp_commit();
        }
        const uint32_t st = sb + (kc % NSTAGE_) * STG_;

        // Batch-load ALL fragments for both k-steps (12 LDSM, MLP-friendly)
        uint32_t af[2][2][4], bf[2][4][4];    // [kst][tile][4]
#pragma unroll
        for (int kst = 0; kst < 2; kst++) {
#pragma unroll
            for (int mt = 0; mt < 2; mt++)
                ldsm_x4(af[kst][mt],
                        st + T_A + sw_off(arow0 + mt * 16, kst * 2 + alane));
#pragma unroll
            for (int nt2 = 0; nt2 < 4; nt2++)
                ldsm_x4(bf[kst][nt2],
                        st + T_B + sw_off(brow0 + nt2 * 16, kst * 2 + blane));
        }
        // Unbroken 32-MMA run
#pragma unroll
        for (int kst = 0; kst < 2; kst++)
#pragma unroll
            for (int mt = 0; mt < 2; mt++)
#pragma unroll
                for (int nt = 0; nt < 8; nt++)
                    mma_f16(acc[mt][nt], af[kst][mt], &bf[kst][nt >> 1][(nt & 1) * 2]);
        __syncthreads();
    }

    // Epilogue: add bias (if any), store
    const int r0 = bm + wm * 32 + (lid >> 2);
    const int cq = (lid & 3) * 2;
#pragma unroll
    for (int mt = 0; mt < 2; mt++) {
#pragma unroll
        for (int nt = 0; nt < 8; nt++) {
            int col = bn + wn * 64 + nt * 8 + cq;
            float bx = 0.0f, by = 0.0f;
            if (bias) { bx = bias[col]; by = bias[col + 1]; }
            store2(C, (size_t)(r0 + mt * 16) * N + col,
                   acc[mt][nt][0] + bx, acc[mt][nt][1] + by);
            store2(C, (size_t)(r0 + mt * 16 + 8) * N + col,
                   acc[mt][nt][2] + bx, acc[mt][nt][3] + by);
        }
    }
}

// Split-K reduce: out[i] = p0[i] + p1[i] + bias[col]
__global__ void reduce_splitk(const float* __restrict__ part, const float* __restrict__ bias,
                              float* __restrict__ out, int n4, size_t zstride4, int Nmask4)
{
    int i = blockIdx.x * blockDim.x + threadIdx.x;
    if (i >= n4) return;
    float4 a = reinterpret_cast<const float4*>(part)[i];
    float4 b = reinterpret_cast<const float4*>(part)[i + zstride4];
    int col = (i & Nmask4) * 4;
    float4 v;
    v.x = a.x + b.x + bias[col + 0];
    v.y = a.y + b.y + bias[col + 1];
    v.z = a.z + b.z + bias[col + 2];
    v.w = a.w + b.w + bias[col + 3];
    reinterpret_cast<float4*>(out)[i] = v;
}

// ---------------------------------------------------------------------------
// Scan:  h_t = a*h_{t-1} + b_t, a = sigmoid(A[h]); chunked over L.
// Vectorized: 2 h-columns per thread via __half2 (b fp16, accum fp32).
// ---------------------------------------------------------------------------
__global__ void scan_reduceA2(const __half2* __restrict__ bbuf, const float* __restrict__ Araw,
                              float2* __restrict__ carry)
{
    int idx = blockIdx.x * blockDim.x + threadIdx.x;   // [B, NC, H/2]
    int h2 = idx & (H_ / 2 - 1);
    int c = (idx >> 11) & (NC_ - 1);
    int bb = idx >> 15;
    float ax = dsigmoid(Araw[2 * h2]);
    float ay = dsigmoid(Araw[2 * h2 + 1]);
    size_t base = ((size_t)bb * L_ + (size_t)c * CHUNK_) * (H_ / 2) + h2;
    float sx = 0.0f, sy = 0.0f;
#pragma unroll 8
    for (int i = 0; i < CHUNK_; i++) {
        float2 v = __half22float2(bbuf[base + (size_t)i * (H_ / 2)]);
        sx = fmaf(ax, sx, v.x);
        sy = fmaf(ay, sy, v.y);
    }
    carry[idx] = make_float2(sx, sy);
}

__global__ void scan_phaseB2(const float2* __restrict__ carry, const float* __restrict__ Araw,
                             float2* __restrict__ hprev)
{
    int idx = blockIdx.x * blockDim.x + threadIdx.x;   // [B, H/2]
    int h2 = idx & (H_ / 2 - 1);
    int bb = idx >> 11;
    float ax = dsigmoid(Araw[2 * h2]);
    float ay = dsigmoid(Araw[2 * h2 + 1]);
    float aCx = ax, aCy = ay;
#pragma unroll
    for (int i = 0; i < 7; i++) { aCx *= aCx; aCy *= aCy; }   // a^128
    float rx = 0.0f, ry = 0.0f;
#pragma unroll
    for (int c = 0; c < NC_; c++) {
        size_t off = ((size_t)bb * NC_ + c) * (H_ / 2) + h2;
        hprev[off] = make_float2(rx, ry);
        float2 cv = carry[off];
        rx = fmaf(aCx, rx, cv.x);
        ry = fmaf(aCy, ry, cv.y);
    }
}

__global__ void scan_phaseC2(const __half2* __restrict__ bbuf, const float* __restrict__ Araw,
                             const float2* __restrict__ hprev,
                             __half2* __restrict__ hh)
{
    int idx = blockIdx.x * blockDim.x + threadIdx.x;   // [B, NC, H/2]
    int h2 = idx & (H_ / 2 - 1);
    int c = (idx >> 11) & (NC_ - 1);
    int bb = idx >> 15;
    float ax = dsigmoid(Araw[2 * h2]);
    float ay = dsigmoid(Araw[2 * h2 + 1]);
    float2 Hp = hprev[idx];
    size_t base = ((size_t)bb * L_ + (size_t)c * CHUNK_) * (H_ / 2) + h2;
    float sx = 0.0f, sy = 0.0f, px = 1.0f, py = 1.0f;
#pragma unroll 8
    for (int i = 0; i < CHUNK_; i++) {
        size_t off = base + (size_t)i * (H_ / 2);
        float2 v = __half22float2(bbuf[off]);
        px *= ax; py *= ay;                    // a^(i+1)
        sx = fmaf(ax, sx, v.x);                // local inclusive scan
        sy = fmaf(ay, sy, v.y);
        float vx = fmaf(px, Hp.x, sx);         // + carry-in contribution
        float vy = fmaf(py, Hp.y, sy);
        hh[off] = __floats2half2_rn(vx, vy);
    }
}

// ---------------------------------------------------------------------------
extern "C" void kernel_launch(void* const* d_in, const int* in_sizes, int n_in,
                              void* d_out, int out_size)
{
    const float* x  = (const float*)d_in[0];   // [B, L, D]
    const float* WB = (const float*)d_in[1];   // [H, D]
    const float* bB = (const float*)d_in[2];   // [H]
    const float* WC = (const float*)d_in[3];   // [D, H]
    const float* bC = (const float*)d_in[4];   // [D]
    const float* A  = (const float*)d_in[5];   // [H]
    float* out = (float*)d_out;                // [B, L, D]

    float *arena, *carry, *hprev;
    __half *xh, *wbh, *wch, *hh;
    cudaGetSymbolAddress((void**)&arena, g_b);
    cudaGetSymbolAddress((void**)&carry, g_carry);
    cudaGetSymbolAddress((void**)&hprev, g_hprev);
    cudaGetSymbolAddress((void**)&xh, g_xh);
    cudaGetSymbolAddress((void**)&wbh, g_wbh);
    cudaGetSymbolAddress((void**)&wch, g_wch);
    cudaGetSymbolAddress((void**)&hh, g_hh);

    __half* bh = reinterpret_cast<__half*>(arena);        // front 64 MB: b fp16
    float* parts = arena + (size_t)16 * 1024 * 1024;      // back 64 MB: split-K partials

    const int SMEM_G = NSTAGE_ * STG_;     // 96 KB -> 2 CTAs/SM
    cudaFuncSetAttribute(gemm_fp16<__half>, cudaFuncAttributeMaxDynamicSharedMemorySize, SMEM_G);
    cudaFuncSetAttribute(gemm_fp16<float>, cudaFuncAttributeMaxDynamicSharedMemorySize, SMEM_G);

    // Convert x, WB, WC to fp16 in ONE launch
    const int n1 = M_ * D_ / 4, n2 = H_ * D_ / 4, n3 = D_ * H_ / 4;
    conv_all_h<<<(n1 + n2 + n3 + 255) / 256, 256>>>(x, xh, n1, WB, wbh, n2, WC, wch, n3);

    // GEMM1: b = x @ WB^T + bB   (M=8192, N=4096, K=256), fp16 output
    gemm_fp16<__half><<<dim3(H_ / BN_, M_ / BM_, 1), 256, SMEM_G>>>(
        xh, wbh, bB, bh, H_, D_, D_, 0);

    // Scan over L (half2-vectorized: 2 h-columns per thread)
    scan_reduceA2<<<(B_ * NC_ * H_ / 2) / 256, 256>>>(
        (const __half2*)bh, A, (float2*)carry);
    scan_phaseB2<<<(B_ * H_ / 2) / 256, 256>>>(
        (const float2*)carry, A, (float2*)hprev);
    scan_phaseC2<<<(B_ * NC_ * H_ / 2) / 256, 256>>>(
        (const __half2*)bh, A, (const float2*)hprev, (__half2*)hh);

    // GEMM2: out = h @ WC^T + bC  (M=8192, N=256, K=4096), split-K=2.
    const size_t zstride = (size_t)M_ * D_;
    gemm_fp16<float><<<dim3(D_ / BN_, M_ / BM_, 2), 256, SMEM_G>>>(
        hh, wch, nullptr, parts, D_, H_, H_ / 2, zstride);
    reduce_splitk<<<(M_ * D_ / 4 + 255) / 256, 256>>>(
        parts, bC, out, M_ * D_ / 4, zstride / 4, (D_ / 4) - 1);
}

// round 17
// speedup vs baseline: 1.0849x; 1.0849x over previous
#include <cuda_runtime.h>
#include <cuda_fp16.h>
#include <cstdint>
#include <math.h>

// ---------------------------------------------------------------------------
// Problem constants
// ---------------------------------------------------------------------------
#define B_ 4
#define L_ 2048
#define D_ 256
#define H_ 4096
#define M_ (B_ * L_)          // 8192
#define CHUNK_ 128
#define NC_ (L_ / CHUNK_)     // 16

// ---------------------------------------------------------------------------
// Scratch (device globals; no allocation allowed)
// g_b front 64MB: b fp16 [M,H]. Back region (offset 16M floats): GEMM2
// split-K fp32 partials (2 x M x D). Disjoint lifetimes guaranteed by layout.
// ---------------------------------------------------------------------------
__device__ __align__(256) float  g_b[(size_t)M_ * H_];      // 128 MB arena
__device__ __align__(256) __half g_hh[(size_t)M_ * H_];     // h fp16
__device__ __align__(256) __half g_xh[(size_t)M_ * D_];
__device__ __align__(256) __half g_wbh[(size_t)H_ * D_];
__device__ __align__(256) __half g_wch[(size_t)D_ * H_];
__device__ __align__(256) float  g_carry[B_ * NC_ * H_];

// ---------------------------------------------------------------------------
// PTX helpers (baseline ISA only: cp.async / ldmatrix / mma.sync)
// ---------------------------------------------------------------------------
__device__ __forceinline__ uint32_t smem_to_u32(const void* p) {
    uint32_t a;
    asm("{ .reg .u64 t; cvta.to.shared.u64 t, %1; cvt.u32.u64 %0, t; }" : "=r"(a) : "l"(p));
    return a;
}
__device__ __forceinline__ void cp_async16(uint32_t dst, const void* src) {
    asm volatile("cp.async.cg.shared.global [%0], [%1], 16;" :: "r"(dst), "l"(src) : "memory");
}
__device__ __forceinline__ void cp_commit() {
    asm volatile("cp.async.commit_group;" ::: "memory");
}
__device__ __forceinline__ void cp_wait4() {
    asm volatile("cp.async.wait_group 4;" ::: "memory");
}
__device__ __forceinline__ void ldsm_x4(uint32_t* r, uint32_t addr) {
    asm volatile("ldmatrix.sync.aligned.m8n8.x4.shared.b16 {%0,%1,%2,%3}, [%4];"
                 : "=r"(r[0]), "=r"(r[1]), "=r"(r[2]), "=r"(r[3]) : "r"(addr));
}
__device__ __forceinline__ void mma_f16(float* c, const uint32_t* a, const uint32_t* b) {
    asm volatile(
        "mma.sync.aligned.m16n8k16.row.col.f32.f16.f16.f32 "
        "{%0,%1,%2,%3}, {%4,%5,%6,%7}, {%8,%9}, {%0,%1,%2,%3};"
        : "+f"(c[0]), "+f"(c[1]), "+f"(c[2]), "+f"(c[3])
        : "r"(a[0]), "r"(a[1]), "r"(a[2]), "r"(a[3]), "r"(b[0]), "r"(b[1]));
}

// Swizzle: 64B rows, 4x 16B lanes; lane ^= (row%4) ^ ((row/4)%4)
__device__ __forceinline__ uint32_t sw_off(int row, int lane) {
    return (uint32_t)(row * 64 + ((lane ^ (row & 3) ^ ((row >> 2) & 3)) << 4));
}

__device__ __forceinline__ float dsigmoid(float x) { return 1.0f / (1.0f + expf(-x)); }

// Output store helpers
__device__ __forceinline__ void store2(float* C, size_t off, float vx, float vy) {
    *reinterpret_cast<float2*>(C + off) = make_float2(vx, vy);
}
__device__ __forceinline__ void store2(__half* C, size_t off, float vx, float vy) {
    *reinterpret_cast<__half2*>(C + off) = __floats2half2_rn(vx, vy);
}

// ---------------------------------------------------------------------------
// Merged fp32 -> fp16 convert: x (n1), WB (n2), WC (n3) in one launch.
// ---------------------------------------------------------------------------
__global__ void conv_all_h(const float* __restrict__ s1, __half* __restrict__ d1, int n1,
                           const float* __restrict__ s2, __half* __restrict__ d2, int n2,
                           const float* __restrict__ s3, __half* __restrict__ d3, int n3)
{
    int i = blockIdx.x * blockDim.x + threadIdx.x;
    const float* s; __half* d; int j = i;
    if (j < n1) { s = s1; d = d1; }
    else if ((j -= n1) < n2) { s = s2; d = d2; }
    else if ((j -= n2) < n3) { s = s3; d = d3; }
    else return;
    float4 v = reinterpret_cast<const float4*>(s)[j];
    reinterpret_cast<__half2*>(d)[2 * j + 0] = __halves2half2(__float2half_rn(v.x), __float2half_rn(v.y));
    reinterpret_cast<__half2*>(d)[2 * j + 1] = __halves2half2(__float2half_rn(v.z), __float2half_rn(v.w));
}

// ---------------------------------------------------------------------------
// Single-stream fp16 GEMM (NT) via mma.sync, templated output type:
//   C[M,N] (+)= Aw[M,Klen] @ (Bw[N,Klen])^T (+ bias[N])
// BM=128, BN=128, BK=32; 8 warps (4m x 2n), warp tile 32x64.
// 6-stage cp.async pipeline; 16KB/stage -> 96KB smem -> 2 CTAs/SM.
// Mainloop = R15 interleaved form (ptxas schedules it best; hand reorders
// verified worse in R7/R16).
// ---------------------------------------------------------------------------
#define BM_ 128
#define BN_ 128
#define BK_ 32
#define NSTAGE_ 6
#define STG_ 16384
#define T_A 0
#define T_B 8192

__device__ __forceinline__ void load_stage(
    uint32_t st, int tid, const char* Aw, const char* Bw,
    size_t rowbytes, int bm, int bn, int k0byte)
{
#pragma unroll
    for (int i = 0; i < 2; i++) {
        int l = tid + i * 256;          // 0..511 lanes of 16B
        int r = l >> 2, c = l & 3;
        uint32_t sw = sw_off(r, c);
        size_t ga = (size_t)(bm + r) * rowbytes + k0byte + c * 16;
        size_t gb = (size_t)(bn + r) * rowbytes + k0byte + c * 16;
        cp_async16(st + T_A + sw, Aw + ga);
        cp_async16(st + T_B + sw, Bw + gb);
    }
}

template <typename TOut>
__global__ __launch_bounds__(256, 2)
void gemm_fp16(const __half* __restrict__ Aw, const __half* __restrict__ Bw,
               const float* __restrict__ bias, TOut* __restrict__ C,
               int N, int K, int Klen, size_t zstride)
{
    extern __shared__ char smem[];
    const uint32_t sb = smem_to_u32(smem);
    const int tid = threadIdx.x;
    const int wid = tid >> 5, lid = tid & 31;
    const int wm = wid & 3, wn = wid >> 2;        // 4(m) x 2(n) warp grid
    const int bm = blockIdx.y * BM_;
    const int bn = blockIdx.x * BN_;
    const size_t rowbytes = (size_t)K * 2;
    const int NKC = Klen / BK_;
    const size_t kofs = (size_t)blockIdx.z * Klen * 2;

    const char* pA = (const char*)Aw + kofs;
    const char* pB = (const char*)Bw + kofs;
    C += (size_t)blockIdx.z * zstride;

    float acc[2][8][4];
#pragma unroll
    for (int mt = 0; mt < 2; mt++)
#pragma unroll
        for (int nt = 0; nt < 8; nt++)
#pragma unroll
            for (int j = 0; j < 4; j++) acc[mt][nt][j] = 0.0f;

    // Prologue: stages 0..4
#pragma unroll
    for (int s = 0; s < NSTAGE_ - 1; s++) {
        if (s < NKC) load_stage(sb + s * STG_, tid, pA, pB, rowbytes, bm, bn, s * BK_ * 2);
        cp_commit();
    }

#pragma unroll 1
    for (int kc = 0; kc < NKC; kc++) {
        cp_wait4();
        __syncthreads();
        {
            int nx = kc + NSTAGE_ - 1;
            if (nx < NKC)
                load_stage(sb + (nx % NSTAGE_) * STG_, tid, pA, pB, rowbytes, bm, bn, nx * BK_ * 2);
            cp_commit();
        }
        const uint32_t st = sb + (kc % NSTAGE_) * STG_;

#pragma unroll
        for (int kst = 0; kst < 2; kst++) {
            uint32_t af[2][4], bf[4][4];
#pragma unroll
            for (int mt = 0; mt < 2; mt++) {
                int row = wm * 32 + mt * 16 + (lid & 15);
                int lane = kst * 2 + (lid >> 4);
                ldsm_x4(af[mt], st + T_A + sw_off(row, lane));
            }
#pragma unroll
            for (int nt2 = 0; nt2 < 4; nt2++) {
                int row = wn * 64 + nt2 * 16 + (lid & 7) + ((lid >> 4) << 3);
                int lane = kst * 2 + ((lid >> 3) & 1);
                ldsm_x4(bf[nt2], st + T_B + sw_off(row, lane));
            }
#pragma unroll
            for (int mt = 0; mt < 2; mt++)
#pragma unroll
                for (int nt = 0; nt < 8; nt++)
                    mma_f16(acc[mt][nt], af[mt], &bf[nt >> 1][(nt & 1) * 2]);
        }
        __syncthreads();
    }

    // Epilogue: add bias (if any), store
    const int r0 = bm + wm * 32 + (lid >> 2);
    const int cq = (lid & 3) * 2;
#pragma unroll
    for (int mt = 0; mt < 2; mt++) {
#pragma unroll
        for (int nt = 0; nt < 8; nt++) {
            int col = bn + wn * 64 + nt * 8 + cq;
            float bx = 0.0f, by = 0.0f;
            if (bias) { bx = bias[col]; by = bias[col + 1]; }
            store2(C, (size_t)(r0 + mt * 16) * N + col,
                   acc[mt][nt][0] + bx, acc[mt][nt][1] + by);
            store2(C, (size_t)(r0 + mt * 16 + 8) * N + col,
                   acc[mt][nt][2] + bx, acc[mt][nt][3] + by);
        }
    }
}

// Split-K reduce: out[i] = p0[i] + p1[i] + bias[col]
__global__ void reduce_splitk(const float* __restrict__ part, const float* __restrict__ bias,
                              float* __restrict__ out, int n4, size_t zstride4, int Nmask4)
{
    int i = blockIdx.x * blockDim.x + threadIdx.x;
    if (i >= n4) return;
    float4 a = reinterpret_cast<const float4*>(part)[i];
    float4 b = reinterpret_cast<const float4*>(part)[i + zstride4];
    int col = (i & Nmask4) * 4;
    float4 v;
    v.x = a.x + b.x + bias[col + 0];
    v.y = a.y + b.y + bias[col + 1];
    v.z = a.z + b.z + bias[col + 2];
    v.w = a.w + b.w + bias[col + 3];
    reinterpret_cast<float4*>(out)[i] = v;
}

// ---------------------------------------------------------------------------
// Scan:  h_t = a*h_{t-1} + b_t, a = sigmoid(A[h]); chunked over L.
// Vectorized: 2 h-columns per thread via __half2 (b fp16, accum fp32).
// Phase B (carry prefix) is fused into phaseC: each block has ONE chunk id,
// so every thread recomputes run = sum_{j<c} aC^(c-1-j)*carry[j] locally
// (identical iterative order => bitwise-identical results).
// ---------------------------------------------------------------------------
__global__ void scan_reduceA2(const __half2* __restrict__ bbuf, const float* __restrict__ Araw,
                              float2* __restrict__ carry)
{
    int idx = blockIdx.x * blockDim.x + threadIdx.x;   // [B, NC, H/2]
    int h2 = idx & (H_ / 2 - 1);
    int c = (idx >> 11) & (NC_ - 1);
    int bb = idx >> 15;
    float ax = dsigmoid(Araw[2 * h2]);
    float ay = dsigmoid(Araw[2 * h2 + 1]);
    size_t base = ((size_t)bb * L_ + (size_t)c * CHUNK_) * (H_ / 2) + h2;
    float sx = 0.0f, sy = 0.0f;
#pragma unroll 8
    for (int i = 0; i < CHUNK_; i++) {
        float2 v = __half22float2(bbuf[base + (size_t)i * (H_ / 2)]);
        sx = fmaf(ax, sx, v.x);
        sy = fmaf(ay, sy, v.y);
    }
    carry[idx] = make_float2(sx, sy);
}

__global__ void scan_phaseC2(const __half2* __restrict__ bbuf, const float* __restrict__ Araw,
                             const float2* __restrict__ carry,
                             __half2* __restrict__ hh)
{
    int idx = blockIdx.x * blockDim.x + threadIdx.x;   // [B, NC, H/2]
    int h2 = idx & (H_ / 2 - 1);
    int c = (idx >> 11) & (NC_ - 1);
    int bb = idx >> 15;
    float ax = dsigmoid(Araw[2 * h2]);
    float ay = dsigmoid(Araw[2 * h2 + 1]);

    // Fused carry prefix: run over chunks j < c (same recurrence as old phaseB)
    float aCx = ax, aCy = ay;
#pragma unroll
    for (int i = 0; i < 7; i++) { aCx *= aCx; aCy *= aCy; }   // a^128
    float rx = 0.0f, ry = 0.0f;
    const size_t cbase = ((size_t)bb * NC_) * (H_ / 2) + h2;
    for (int j = 0; j < c; j++) {
        float2 cv = carry[cbase + (size_t)j * (H_ / 2)];
        rx = fmaf(aCx, rx, cv.x);
        ry = fmaf(aCy, ry, cv.y);
    }

    size_t base = ((size_t)bb * L_ + (size_t)c * CHUNK_) * (H_ / 2) + h2;
    float sx = 0.0f, sy = 0.0f, px = 1.0f, py = 1.0f;
#pragma unroll 8
    for (int i = 0; i < CHUNK_; i++) {
        size_t off = base + (size_t)i * (H_ / 2);
        float2 v = __half22float2(bbuf[off]);
        px *= ax; py *= ay;                    // a^(i+1)
        sx = fmaf(ax, sx, v.x);                // local inclusive scan
        sy = fmaf(ay, sy, v.y);
        float vx = fmaf(px, rx, sx);           // + carry-in contribution
        float vy = fmaf(py, ry, sy);
        hh[off] = __floats2half2_rn(vx, vy);
    }
}

// ---------------------------------------------------------------------------
extern "C" void kernel_launch(void* const* d_in, const int* in_sizes, int n_in,
                              void* d_out, int out_size)
{
    const float* x  = (const float*)d_in[0];   // [B, L, D]
    const float* WB = (const float*)d_in[1];   // [H, D]
    const float* bB = (const float*)d_in[2];   // [H]
    const float* WC = (const float*)d_in[3];   // [D, H]
    const float* bC = (const float*)d_in[4];   // [D]
    const float* A  = (const float*)d_in[5];   // [H]
    float* out = (float*)d_out;                // [B, L, D]

    float *arena, *carry;
    __half *xh, *wbh, *wch, *hh;
    cudaGetSymbolAddress((void**)&arena, g_b);
    cudaGetSymbolAddress((void**)&carry, g_carry);
    cudaGetSymbolAddress((void**)&xh, g_xh);
    cudaGetSymbolAddress((void**)&wbh, g_wbh);
    cudaGetSymbolAddress((void**)&wch, g_wch);
    cudaGetSymbolAddress((void**)&hh, g_hh);

    __half* bh = reinterpret_cast<__half*>(arena);        // front 64 MB: b fp16
    float* parts = arena + (size_t)16 * 1024 * 1024;      // back 64 MB: split-K partials

    const int SMEM_G = NSTAGE_ * STG_;     // 96 KB -> 2 CTAs/SM
    cudaFuncSetAttribute(gemm_fp16<__half>, cudaFuncAttributeMaxDynamicSharedMemorySize, SMEM_G);
    cudaFuncSetAttribute(gemm_fp16<float>, cudaFuncAttributeMaxDynamicSharedMemorySize, SMEM_G);

    // Convert x, WB, WC to fp16 in ONE launch
    const int n1 = M_ * D_ / 4, n2 = H_ * D_ / 4, n3 = D_ * H_ / 4;
    conv_all_h<<<(n1 + n2 + n3 + 255) / 256, 256>>>(x, xh, n1, WB, wbh, n2, WC, wch, n3);

    // GEMM1: b = x @ WB^T + bB   (M=8192, N=4096, K=256), fp16 output
    gemm_fp16<__half><<<dim3(H_ / BN_, M_ / BM_, 1), 256, SMEM_G>>>(
        xh, wbh, bB, bh, H_, D_, D_, 0);

    // Scan over L (half2-vectorized; phaseB fused into phaseC)
    scan_reduceA2<<<(B_ * NC_ * H_ / 2) / 256, 256>>>(
        (const __half2*)bh, A, (float2*)carry);
    scan_phaseC2<<<(B_ * NC_ * H_ / 2) / 256, 256>>>(
        (const __half2*)bh, A, (const float2*)carry, (__half2*)hh);

    // GEMM2: out = h @ WC^T + bC  (M=8192, N=256, K=4096), split-K=2.
    const size_t zstride = (size_t)M_ * D_;
    gemm_fp16<float><<<dim3(D_ / BN_, M_ / BM_, 2), 256, SMEM_G>>>(
        hh, wch, nullptr, parts, D_, H_, H_ / 2, zstride);
    reduce_splitk<<<(M_ * D_ / 4 + 255) / 256, 256>>>(
        parts, bC, out, M_ * D_ / 4, zstride / 4, (D_ / 4) - 1);
}